// round 5
// baseline (speedup 1.0000x reference)
#include <cuda_runtime.h>
#include <cuda_bf16.h>
#include <cuda_fp16.h>
#include <math.h>
#include <stdint.h>

#define HD   1024
#define K2   2048
#define BB   8
#define SS   4096
#define LL   64
#define M512 (BB*LL)

// ---- device scratch ----
__device__ __nv_bfloat16 g_Wt_h[K2 * HD];   // W^T pre-split bf16 hi  [n=2H][h=H]
__device__ __nv_bfloat16 g_Wt_l[K2 * HD];   // W^T pre-split bf16 lo
__device__ __nv_bfloat16 g_Wh_h[M512 * K2];
__device__ __nv_bfloat16 g_Wh_l[M512 * K2];
__device__ float         g_bh[M512];
__device__ float         g_scores[(size_t)M512 * SS];
__device__ __half        g_w_h[(size_t)M512 * SS];
__device__ __half        g_w_l[(size_t)M512 * SS];
__device__ __half        g_c2_h[M512 * K2];
__device__ __half        g_c2_l[M512 * K2];

// ---- helpers ----
__device__ __forceinline__ uint32_t smem_u32(const void* p) {
    uint32_t a;
    asm("{ .reg .u64 t; cvta.to.shared.u64 t, %1; cvt.u32.u64 %0, t; }" : "=r"(a) : "l"(p));
    return a;
}
// bf16 hi/lo split of an fp32 pair
__device__ __forceinline__ void split2(float x0, float x1, uint32_t& h, uint32_t& l) {
    __nv_bfloat162 hh = __floats2bfloat162_rn(x0, x1);
    h = *(uint32_t*)&hh;
    float h0 = __uint_as_float(h << 16);
    float h1 = __uint_as_float(h & 0xFFFF0000u);
    __nv_bfloat162 ll = __floats2bfloat162_rn(x0 - h0, x1 - h1);
    l = *(uint32_t*)&ll;
}
// fp16 hi/lo split of an fp32 pair
__device__ __forceinline__ void split2h(float x0, float x1, uint32_t& h, uint32_t& l) {
    __half2 hh = __floats2half2_rn(x0, x1);
    h = *(uint32_t*)&hh;
    float2 hf = __half22float2(hh);
    __half2 ll = __floats2half2_rn(x0 - hf.x, x1 - hf.y);
    l = *(uint32_t*)&ll;
}
__device__ __forceinline__ uint32_t packh(float x0, float x1) {
    __half2 hh = __floats2half2_rn(x0, x1);
    return *(uint32_t*)&hh;
}
__device__ __forceinline__ void mma_bf16(float* d, const uint32_t* a, uint32_t b0, uint32_t b1) {
    asm volatile(
        "mma.sync.aligned.m16n8k16.row.col.f32.bf16.bf16.f32 "
        "{%0,%1,%2,%3}, {%4,%5,%6,%7}, {%8,%9}, {%0,%1,%2,%3};"
        : "+f"(d[0]), "+f"(d[1]), "+f"(d[2]), "+f"(d[3])
        : "r"(a[0]), "r"(a[1]), "r"(a[2]), "r"(a[3]), "r"(b0), "r"(b1));
}
__device__ __forceinline__ void mma_fp16(float* d, const uint32_t* a, uint32_t b0, uint32_t b1) {
    asm volatile(
        "mma.sync.aligned.m16n8k16.row.col.f32.f16.f16.f32 "
        "{%0,%1,%2,%3}, {%4,%5,%6,%7}, {%8,%9}, {%0,%1,%2,%3};"
        : "+f"(d[0]), "+f"(d[1]), "+f"(d[2]), "+f"(d[3])
        : "r"(a[0]), "r"(a[1]), "r"(a[2]), "r"(a[3]), "r"(b0), "r"(b1));
}
__device__ __forceinline__ void ldmx4(uint32_t* r, uint32_t addr) {
    asm volatile("ldmatrix.sync.aligned.m8n8.x4.shared.b16 {%0,%1,%2,%3}, [%4];"
                 : "=r"(r[0]), "=r"(r[1]), "=r"(r[2]), "=r"(r[3]) : "r"(addr));
}
// byte offset of (row l, elem ko[0..127]) inside a 32KB staged chunk (2B elems)
__device__ __forceinline__ uint32_t bofs(int l, int ko) {
    return ((uint32_t)(ko >> 6) << 13) +
           ((((uint32_t)l << 7) + (uint32_t)((ko & 63) << 1)) ^ (uint32_t)((l & 7) << 4));
}

// ---------------------------------------------------------------------------
// K0: transpose + bf16-split W -> g_Wt_h/g_Wt_l  [n=K2][h=HD]
// ---------------------------------------------------------------------------
__global__ __launch_bounds__(256) void k0_wt(const float* __restrict__ W) {
    __shared__ float tile[32][33];
    int n0 = blockIdx.x * 32, h0 = blockIdx.y * 32;
    int tx = threadIdx.x & 31, ty = threadIdx.x >> 5;   // 32 x 8
    #pragma unroll
    for (int r = 0; r < 4; r++) {
        int h = h0 + ty + r * 8;
        tile[ty + r * 8][tx] = W[(size_t)h * K2 + n0 + tx];
    }
    __syncthreads();
    #pragma unroll
    for (int r = 0; r < 4; r++) {
        int n = n0 + ty + r * 8;
        float x = tile[tx][ty + r * 8];
        __nv_bfloat16 h = __float2bfloat16_rn(x);
        g_Wt_h[(size_t)n * HD + h0 + tx] = h;
        g_Wt_l[(size_t)n * HD + h0 + tx] = __float2bfloat16_rn(x - __bfloat162float(h));
    }
}

// ---------------------------------------------------------------------------
__global__ __launch_bounds__(256) void k_bh(const float* __restrict__ hidden,
                                            const float* __restrict__ bias) {
    int w = (blockIdx.x * 256 + threadIdx.x) >> 5;
    int lane = threadIdx.x & 31;
    int b = w >> 6, l = w & 63;
    const float* hrow = hidden + (l * BB + b) * HD;
    float s = 0.f;
    for (int h = lane; h < HD; h += 32) s += bias[h] * hrow[h];
    #pragma unroll
    for (int o = 16; o; o >>= 1) s += __shfl_xor_sync(0xffffffffu, s, o);
    if (lane == 0) g_bh[w] = s;
}

// ---------------------------------------------------------------------------
// K1 (mma, bf16 3-term): Wh[m,n] = sum_h hidden_row(m)[h] * Wt[n][h]
// ---------------------------------------------------------------------------
__global__ __launch_bounds__(256) void k1_mma(const float* __restrict__ hidden) {
    const int tid = threadIdx.x, w = tid >> 5, lane = tid & 31;
    const int grp = lane >> 2, tig = lane & 3;
    const int m0 = blockIdx.y * 128 + w * 16;
    const int n0 = blockIdx.x * 64;
    int mA = m0 + grp, mB = mA + 8;
    const float* row0 = hidden + ((size_t)((mA & 63) * BB + (mA >> 6))) * HD;
    const float* row1 = hidden + ((size_t)((mB & 63) * BB + (mB >> 6))) * HD;

    float d[8][4];
    #pragma unroll
    for (int i = 0; i < 8; i++) { d[i][0]=d[i][1]=d[i][2]=d[i][3]=0.f; }

    for (int k0 = 0; k0 < HD; k0 += 16) {
        float2 v0 = *(const float2*)(row0 + k0 + tig * 2);
        float2 v2 = *(const float2*)(row0 + k0 + tig * 2 + 8);
        float2 v1 = *(const float2*)(row1 + k0 + tig * 2);
        float2 v3 = *(const float2*)(row1 + k0 + tig * 2 + 8);
        uint32_t ah[4], al[4];
        split2(v0.x, v0.y, ah[0], al[0]);
        split2(v1.x, v1.y, ah[1], al[1]);
        split2(v2.x, v2.y, ah[2], al[2]);
        split2(v3.x, v3.y, ah[3], al[3]);
        uint32_t bh0[8], bh1[8], bl0[8], bl1[8];
        #pragma unroll
        for (int nt = 0; nt < 8; nt++) {
            size_t ro = (size_t)(n0 + nt * 8 + grp) * HD + k0 + 2 * tig;
            bh0[nt] = *(const uint32_t*)(g_Wt_h + ro);
            bh1[nt] = *(const uint32_t*)(g_Wt_h + ro + 8);
            bl0[nt] = *(const uint32_t*)(g_Wt_l + ro);
            bl1[nt] = *(const uint32_t*)(g_Wt_l + ro + 8);
        }
        #pragma unroll
        for (int nt = 0; nt < 8; nt++) mma_bf16(d[nt], ah, bh0[nt], bh1[nt]);
        #pragma unroll
        for (int nt = 0; nt < 8; nt++) mma_bf16(d[nt], al, bh0[nt], bh1[nt]);
        #pragma unroll
        for (int nt = 0; nt < 8; nt++) mma_bf16(d[nt], ah, bl0[nt], bl1[nt]);
    }
    #pragma unroll
    for (int nt = 0; nt < 8; nt++) {
        int np = n0 + nt * 8 + tig * 2;
        uint32_t h01, l01, h23, l23;
        split2(d[nt][0], d[nt][1], h01, l01);
        split2(d[nt][2], d[nt][3], h23, l23);
        *(uint32_t*)(g_Wh_h + (size_t)mA * K2 + np) = h01;
        *(uint32_t*)(g_Wh_l + (size_t)mA * K2 + np) = l01;
        *(uint32_t*)(g_Wh_h + (size_t)mB * K2 + np) = h23;
        *(uint32_t*)(g_Wh_l + (size_t)mB * K2 + np) = l23;
    }
}

// ---------------------------------------------------------------------------
// K2 (mma, bf16 3-term, term-major): scores[l, s] = bh[l] + enc@Wh^T
// ---------------------------------------------------------------------------
__global__ __launch_bounds__(512) void k2_mma(const float* __restrict__ enc) {
    extern __shared__ __align__(128) uint8_t sm[];
    const int tid = threadIdx.x, w = tid >> 5, lane = tid & 31;
    const int grp = lane >> 2, tig = lane & 3;
    const int b = blockIdx.y;
    const int sW = blockIdx.x * 256 + w * 16;
    uint32_t sbase = smem_u32(sm);
    const float* encb = enc + (size_t)b * SS * K2;
    const __nv_bfloat16* Bh = g_Wh_h + (size_t)b * 64 * K2;
    const __nv_bfloat16* Bl = g_Wh_l + (size_t)b * 64 * K2;

    const int q0 = tid, q1 = tid + 512;
    const int l0q = q0 >> 4, ko0q = (q0 & 15) * 8;
    const int l1q = q1 >> 4, ko1q = (q1 & 15) * 8;

    {
        uint4 a  = *(const uint4*)(Bh + (size_t)l0q * K2 + ko0q);
        uint4 bq = *(const uint4*)(Bh + (size_t)l1q * K2 + ko1q);
        uint4 cq = *(const uint4*)(Bl + (size_t)l0q * K2 + ko0q);
        uint4 dq = *(const uint4*)(Bl + (size_t)l1q * K2 + ko1q);
        *(uint4*)(sm + bofs(l0q, ko0q)) = a;
        *(uint4*)(sm + bofs(l1q, ko1q)) = bq;
        *(uint4*)(sm + 16384 + bofs(l0q, ko0q)) = cq;
        *(uint4*)(sm + 16384 + bofs(l1q, ko1q)) = dq;
    }
    __syncthreads();

    float d[8][4];
    #pragma unroll
    for (int i = 0; i < 8; i++) { d[i][0]=d[i][1]=d[i][2]=d[i][3]=0.f; }

    const float* arow = encb + (size_t)(sW + grp) * K2 + tig * 2;

    for (int c = 0; c < 16; c++) {
        int p = c & 1;
        uint4 ph0, ph1, pl0, pl1;
        if (c < 15) {
            int kb = (c + 1) * 128;
            ph0 = *(const uint4*)(Bh + (size_t)l0q * K2 + kb + ko0q);
            ph1 = *(const uint4*)(Bh + (size_t)l1q * K2 + kb + ko1q);
            pl0 = *(const uint4*)(Bl + (size_t)l0q * K2 + kb + ko0q);
            pl1 = *(const uint4*)(Bl + (size_t)l1q * K2 + kb + ko1q);
        }
        #pragma unroll
        for (int ks = 0; ks < 8; ks++) {
            const float* ap = arow + c * 128 + ks * 16;
            float2 v0 = *(const float2*)(ap);
            float2 v2 = *(const float2*)(ap + 8);
            float2 v1 = *(const float2*)(ap + 8 * K2);
            float2 v3 = *(const float2*)(ap + 8 * K2 + 8);
            uint32_t ah[4], al[4];
            split2(v0.x, v0.y, ah[0], al[0]);
            split2(v1.x, v1.y, ah[1], al[1]);
            split2(v2.x, v2.y, ah[2], al[2]);
            split2(v3.x, v3.y, ah[3], al[3]);
            int kol = ks * 16 + (lane & 8);
            uint32_t bh4[4][4], bl4[4][4];
            #pragma unroll
            for (int np = 0; np < 4; np++) {
                int lr = np * 16 + (lane & 7) + ((lane >> 1) & 8);
                uint32_t addr = sbase + (uint32_t)p * 32768 + bofs(lr, kol);
                ldmx4(bh4[np], addr);
                ldmx4(bl4[np], addr + 16384);
            }
            #pragma unroll
            for (int np = 0; np < 4; np++) {
                mma_bf16(d[2*np],   ah, bh4[np][0], bh4[np][1]);
                mma_bf16(d[2*np+1], ah, bh4[np][2], bh4[np][3]);
            }
            #pragma unroll
            for (int np = 0; np < 4; np++) {
                mma_bf16(d[2*np],   al, bh4[np][0], bh4[np][1]);
                mma_bf16(d[2*np+1], al, bh4[np][2], bh4[np][3]);
            }
            #pragma unroll
            for (int np = 0; np < 4; np++) {
                mma_bf16(d[2*np],   ah, bl4[np][0], bl4[np][1]);
                mma_bf16(d[2*np+1], ah, bl4[np][2], bl4[np][3]);
            }
        }
        if (c < 15) {
            __syncthreads();
            uint32_t bo = (uint32_t)(p ^ 1) * 32768;
            *(uint4*)(sm + bo + bofs(l0q, ko0q)) = ph0;
            *(uint4*)(sm + bo + bofs(l1q, ko1q)) = ph1;
            *(uint4*)(sm + bo + 16384 + bofs(l0q, ko0q)) = pl0;
            *(uint4*)(sm + bo + 16384 + bofs(l1q, ko1q)) = pl1;
            __syncthreads();
        }
    }
    #pragma unroll
    for (int nt = 0; nt < 8; nt++) {
        int li = nt * 8 + tig * 2;
        float b0v = g_bh[b * 64 + li], b1v = g_bh[b * 64 + li + 1];
        size_t r0 = (size_t)(b * 64 + li) * SS, r1 = r0 + SS;
        int sl = sW + grp;
        g_scores[r0 + sl]     = d[nt][0] + b0v;
        g_scores[r1 + sl]     = d[nt][1] + b1v;
        g_scores[r0 + sl + 8] = d[nt][2] + b0v;
        g_scores[r1 + sl + 8] = d[nt][3] + b1v;
    }
}

// ---------------------------------------------------------------------------
// K3: softmax; emit out_w [B,S,L] fp32 and weights fp16 hi/lo
// ---------------------------------------------------------------------------
__global__ __launch_bounds__(256) void k3_softmax(float* __restrict__ out_w) {
    int row = blockIdx.x;
    const float* p = g_scores + (size_t)row * SS;
    int t = threadIdx.x;
    __shared__ float red[256];
    float v[16];
    float m = -1e30f;
    #pragma unroll
    for (int i = 0; i < 16; i++) { v[i] = p[t + i * 256]; m = fmaxf(m, v[i]); }
    red[t] = m; __syncthreads();
    #pragma unroll
    for (int o = 128; o; o >>= 1) { if (t < o) red[t] = fmaxf(red[t], red[t + o]); __syncthreads(); }
    m = red[0]; __syncthreads();
    float s = 0.f;
    #pragma unroll
    for (int i = 0; i < 16; i++) { v[i] = expf(v[i] - m); s += v[i]; }
    red[t] = s; __syncthreads();
    #pragma unroll
    for (int o = 128; o; o >>= 1) { if (t < o) red[t] += red[t + o]; __syncthreads(); }
    float inv = 1.f / red[0];
    int b = row >> 6, l = row & 63;
    #pragma unroll
    for (int i = 0; i < 16; i += 2) {
        int si = t * 2 + i * 256;
        float w0 = p[si], w1 = p[si + 1];
        w0 = expf(w0 - m) * inv;  w1 = expf(w1 - m) * inv;
        out_w[((size_t)b * SS + si) * LL + l] = w0;
        out_w[((size_t)b * SS + si + 1) * LL + l] = w1;
        uint32_t h, lo2;
        split2h(w0, w1, h, lo2);
        *(uint32_t*)(g_w_h + (size_t)row * SS + si) = h;
        *(uint32_t*)(g_w_l + (size_t)row * SS + si) = lo2;
    }
}

// ---------------------------------------------------------------------------
// K4 (mma, fp16 2-term): ctx2[l, k] = sum_s w[l,s] * enc[s,k]; emit fp16 hi/lo
// ---------------------------------------------------------------------------
__global__ __launch_bounds__(512) void k4_mma(const float* __restrict__ enc) {
    extern __shared__ __align__(128) uint8_t sm[];
    const int tid = threadIdx.x, w = tid >> 5, lane = tid & 31;
    const int grp = lane >> 2, tig = lane & 3;
    const int wk = w & 7, sgrp = w >> 3;
    const int b = blockIdx.y;
    const int kb0 = blockIdx.x * 128;
    const int kW = kb0 + wk * 16;
    uint32_t sbase = smem_u32(sm);
    const float* encb = enc + (size_t)b * SS * K2;
    const __half* Bh = g_w_h + (size_t)b * 64 * SS;
    const __half* Bl = g_w_l + (size_t)b * 64 * SS;

    const int q0 = tid, q1 = tid + 512;
    const int l0q = q0 >> 4, ko0q = (q0 & 15) * 8;
    const int l1q = q1 >> 4, ko1q = (q1 & 15) * 8;

    {
        uint4 a  = *(const uint4*)(Bh + (size_t)l0q * SS + ko0q);
        uint4 bq = *(const uint4*)(Bh + (size_t)l1q * SS + ko1q);
        uint4 cq = *(const uint4*)(Bl + (size_t)l0q * SS + ko0q);
        uint4 dq = *(const uint4*)(Bl + (size_t)l1q * SS + ko1q);
        *(uint4*)(sm + bofs(l0q, ko0q)) = a;
        *(uint4*)(sm + bofs(l1q, ko1q)) = bq;
        *(uint4*)(sm + 16384 + bofs(l0q, ko0q)) = cq;
        *(uint4*)(sm + 16384 + bofs(l1q, ko1q)) = dq;
    }
    __syncthreads();

    float d[8][4];
    #pragma unroll
    for (int i = 0; i < 8; i++) { d[i][0]=d[i][1]=d[i][2]=d[i][3]=0.f; }

    for (int c = 0; c < 32; c++) {
        int p = c & 1;
        uint4 ph0, ph1, pl0, pl1;
        if (c < 31) {
            int s1 = (c + 1) * 128;
            ph0 = *(const uint4*)(Bh + (size_t)l0q * SS + s1 + ko0q);
            ph1 = *(const uint4*)(Bh + (size_t)l1q * SS + s1 + ko1q);
            pl0 = *(const uint4*)(Bl + (size_t)l0q * SS + s1 + ko0q);
            pl1 = *(const uint4*)(Bl + (size_t)l1q * SS + s1 + ko1q);
        }
        #pragma unroll
        for (int ks2 = 0; ks2 < 4; ks2++) {
            int ks = ks2 * 2 + sgrp;
            int s0 = c * 128 + ks * 16;
            const float* ap = encb + (size_t)(s0 + tig * 2) * K2 + kW + grp;
            uint32_t ah[4];
            ah[0] = packh(ap[0],          ap[K2]);
            ah[1] = packh(ap[8],          ap[K2 + 8]);
            ah[2] = packh(ap[8 * K2],     ap[9 * K2]);
            ah[3] = packh(ap[8 * K2 + 8], ap[9 * K2 + 8]);
            int kol = ks * 16 + (lane & 8);
            uint32_t bh4[4][4], bl4[4][4];
            #pragma unroll
            for (int np = 0; np < 4; np++) {
                int lr = np * 16 + (lane & 7) + ((lane >> 1) & 8);
                uint32_t addr = sbase + (uint32_t)p * 32768 + bofs(lr, kol);
                ldmx4(bh4[np], addr);
                ldmx4(bl4[np], addr + 16384);
            }
            #pragma unroll
            for (int np = 0; np < 4; np++) {
                mma_fp16(d[2*np],   ah, bh4[np][0], bh4[np][1]);
                mma_fp16(d[2*np+1], ah, bh4[np][2], bh4[np][3]);
            }
            #pragma unroll
            for (int np = 0; np < 4; np++) {
                mma_fp16(d[2*np],   ah, bl4[np][0], bl4[np][1]);
                mma_fp16(d[2*np+1], ah, bl4[np][2], bl4[np][3]);
            }
        }
        if (c < 31) {
            __syncthreads();
            uint32_t bo = (uint32_t)(p ^ 1) * 32768;
            *(uint4*)(sm + bo + bofs(l0q, ko0q)) = ph0;
            *(uint4*)(sm + bo + bofs(l1q, ko1q)) = ph1;
            *(uint4*)(sm + bo + 16384 + bofs(l0q, ko0q)) = pl0;
            *(uint4*)(sm + bo + 16384 + bofs(l1q, ko1q)) = pl1;
            __syncthreads();
        }
    }

    __syncthreads();
    float* acc = (float*)sm;
    {
        int base = sgrp * 8192;
        #pragma unroll
        for (int nt = 0; nt < 8; nt++) {
            int li = nt * 8 + tig * 2;
            int kr = wk * 16 + grp;
            acc[base + li * 128 + kr]           = d[nt][0];
            acc[base + (li + 1) * 128 + kr]     = d[nt][1];
            acc[base + li * 128 + kr + 8]       = d[nt][2];
            acc[base + (li + 1) * 128 + kr + 8] = d[nt][3];
        }
    }
    __syncthreads();
    {
        int l = tid >> 3, kq = (tid & 7) * 16;
        const float* s0p = acc + l * 128 + kq;
        const float* s1p = acc + 8192 + l * 128 + kq;
        uint32_t hb[8], lb[8];
        #pragma unroll
        for (int j = 0; j < 8; j++) {
            float x0 = s0p[2 * j] + s1p[2 * j];
            float x1 = s0p[2 * j + 1] + s1p[2 * j + 1];
            split2h(x0, x1, hb[j], lb[j]);
        }
        size_t ro = (size_t)(b * 64 + l) * K2 + kb0 + kq;
        *(uint4*)(g_c2_h + ro)     = make_uint4(hb[0], hb[1], hb[2], hb[3]);
        *(uint4*)(g_c2_h + ro + 8) = make_uint4(hb[4], hb[5], hb[6], hb[7]);
        *(uint4*)(g_c2_l + ro)     = make_uint4(lb[0], lb[1], lb[2], lb[3]);
        *(uint4*)(g_c2_l + ro + 8) = make_uint4(lb[4], lb[5], lb[6], lb[7]);
    }
}

// ---------------------------------------------------------------------------
// K5 (mma, fp16 2-term): out[m, h] = bias[h] + sum_k ctx2[m,k] * W[h,k]
// ---------------------------------------------------------------------------
__global__ __launch_bounds__(256) void k5_mma(const float* __restrict__ W,
                                              const float* __restrict__ bias,
                                              float* __restrict__ out) {
    const int tid = threadIdx.x, w = tid >> 5, lane = tid & 31;
    const int grp = lane >> 2, tig = lane & 3;
    const int m0 = blockIdx.y * 128 + w * 16;
    const int n0 = blockIdx.x * 32;
    int mA = m0 + grp, mB = mA + 8;
    const uint32_t* a0h = (const uint32_t*)(g_c2_h + (size_t)mA * K2) + tig;
    const uint32_t* a0l = (const uint32_t*)(g_c2_l + (size_t)mA * K2) + tig;
    const uint32_t* a1h = (const uint32_t*)(g_c2_h + (size_t)mB * K2) + tig;
    const uint32_t* a1l = (const uint32_t*)(g_c2_l + (size_t)mB * K2) + tig;

    float d[4][4];
    #pragma unroll
    for (int i = 0; i < 4; i++) { d[i][0]=d[i][1]=d[i][2]=d[i][3]=0.f; }

    for (int k0 = 0; k0 < K2; k0 += 16) {
        int ku = k0 >> 1;
        uint32_t ah[4], al[4];
        ah[0] = a0h[ku];     al[0] = a0l[ku];
        ah[1] = a1h[ku];     al[1] = a1l[ku];
        ah[2] = a0h[ku + 4]; al[2] = a0l[ku + 4];
        ah[3] = a1h[ku + 4]; al[3] = a1l[ku + 4];
        uint32_t bh0[4], bh1[4];
        #pragma unroll
        for (int nt = 0; nt < 4; nt++) {
            const float* wp = W + (size_t)(n0 + nt * 8 + grp) * K2 + k0 + 2 * tig;
            float2 u0 = *(const float2*)(wp);
            float2 u1 = *(const float2*)(wp + 8);
            bh0[nt] = packh(u0.x, u0.y);
            bh1[nt] = packh(u1.x, u1.y);
        }
        #pragma unroll
        for (int nt = 0; nt < 4; nt++) mma_fp16(d[nt], ah, bh0[nt], bh1[nt]);
        #pragma unroll
        for (int nt = 0; nt < 4; nt++) mma_fp16(d[nt], al, bh0[nt], bh1[nt]);
    }
    #pragma unroll
    for (int nt = 0; nt < 4; nt++) {
        int hp = n0 + nt * 8 + tig * 2;
        float2 bv = *(const float2*)(bias + hp);
        float2 o0 = {d[nt][0] + bv.x, d[nt][1] + bv.y};
        float2 o1 = {d[nt][2] + bv.x, d[nt][3] + bv.y};
        *(float2*)(out + (size_t)mA * HD + hp) = o0;
        *(float2*)(out + (size_t)mB * HD + hp) = o1;
    }
}

// ---------------------------------------------------------------------------
extern "C" void kernel_launch(void* const* d_in, const int* in_sizes, int n_in,
                              void* d_out, int out_size) {
    (void)in_sizes; (void)n_in; (void)out_size;
    const float* hidden = (const float*)d_in[0];
    const float* enc    = (const float*)d_in[1];
    const float* W      = (const float*)d_in[2];
    const float* bias   = (const float*)d_in[3];
    float* out_ctx = (float*)d_out;
    float* out_w   = (float*)d_out + (size_t)BB * LL * HD;

    cudaFuncSetAttribute(k2_mma, cudaFuncAttributeMaxDynamicSharedMemorySize, 65536);
    cudaFuncSetAttribute(k4_mma, cudaFuncAttributeMaxDynamicSharedMemorySize, 65536);

    k0_wt<<<dim3(64, 32), 256>>>(W);
    k_bh<<<64, 256>>>(hidden, bias);
    k1_mma<<<dim3(32, 4), 256>>>(hidden);
    k2_mma<<<dim3(16, 8), 512, 65536>>>(enc);
    k3_softmax<<<512, 256>>>(out_w);
    k4_mma<<<dim3(16, 8), 512, 65536>>>(enc);
    k5_mma<<<dim3(32, 4), 256>>>(W, bias, out_ctx);
}

// round 6
// speedup vs baseline: 1.4273x; 1.4273x over previous
#include <cuda_runtime.h>
#include <cuda_bf16.h>
#include <cuda_fp16.h>
#include <math.h>
#include <stdint.h>

#define HD   1024
#define K2   2048
#define BB   8
#define SS   4096
#define LL   64
#define M512 (BB*LL)

// ---- device scratch ----
__device__ __nv_bfloat16 g_Wt_h[K2 * HD];   // W^T bf16 hi  [n=2H][h=H]
__device__ __nv_bfloat16 g_Wt_l[K2 * HD];   // W^T bf16 lo
__device__ __half        g_W16[HD * K2];    // W fp16 hi    [h][2H]
__device__ __nv_bfloat16 g_Wh_h[M512 * K2];
__device__ __nv_bfloat16 g_Wh_l[M512 * K2];
__device__ float         g_bh[M512];
__device__ float         g_scores[(size_t)M512 * SS];
__device__ float         g_m[M512];
__device__ float         g_inv[M512];
__device__ __half        g_w_h[(size_t)M512 * SS];
__device__ __half        g_w_l[(size_t)M512 * SS];
__device__ __half        g_c2_h[M512 * K2];
__device__ __half        g_c2_l[M512 * K2];

// ---- helpers ----
__device__ __forceinline__ uint32_t smem_u32(const void* p) {
    uint32_t a;
    asm("{ .reg .u64 t; cvta.to.shared.u64 t, %1; cvt.u32.u64 %0, t; }" : "=r"(a) : "l"(p));
    return a;
}
__device__ __forceinline__ void split2(float x0, float x1, uint32_t& h, uint32_t& l) {
    __nv_bfloat162 hh = __floats2bfloat162_rn(x0, x1);
    h = *(uint32_t*)&hh;
    float h0 = __uint_as_float(h << 16);
    float h1 = __uint_as_float(h & 0xFFFF0000u);
    __nv_bfloat162 ll = __floats2bfloat162_rn(x0 - h0, x1 - h1);
    l = *(uint32_t*)&ll;
}
__device__ __forceinline__ void split2h(float x0, float x1, uint32_t& h, uint32_t& l) {
    __half2 hh = __floats2half2_rn(x0, x1);
    h = *(uint32_t*)&hh;
    float2 hf = __half22float2(hh);
    __half2 ll = __floats2half2_rn(x0 - hf.x, x1 - hf.y);
    l = *(uint32_t*)&ll;
}
__device__ __forceinline__ uint32_t packh(float x0, float x1) {
    __half2 hh = __floats2half2_rn(x0, x1);
    return *(uint32_t*)&hh;
}
__device__ __forceinline__ void mma_bf16(float* d, const uint32_t* a, uint32_t b0, uint32_t b1) {
    asm volatile(
        "mma.sync.aligned.m16n8k16.row.col.f32.bf16.bf16.f32 "
        "{%0,%1,%2,%3}, {%4,%5,%6,%7}, {%8,%9}, {%0,%1,%2,%3};"
        : "+f"(d[0]), "+f"(d[1]), "+f"(d[2]), "+f"(d[3])
        : "r"(a[0]), "r"(a[1]), "r"(a[2]), "r"(a[3]), "r"(b0), "r"(b1));
}
__device__ __forceinline__ void mma_fp16(float* d, const uint32_t* a, uint32_t b0, uint32_t b1) {
    asm volatile(
        "mma.sync.aligned.m16n8k16.row.col.f32.f16.f16.f32 "
        "{%0,%1,%2,%3}, {%4,%5,%6,%7}, {%8,%9}, {%0,%1,%2,%3};"
        : "+f"(d[0]), "+f"(d[1]), "+f"(d[2]), "+f"(d[3])
        : "r"(a[0]), "r"(a[1]), "r"(a[2]), "r"(a[3]), "r"(b0), "r"(b1));
}
__device__ __forceinline__ void ldmx4(uint32_t* r, uint32_t addr) {
    asm volatile("ldmatrix.sync.aligned.m8n8.x4.shared.b16 {%0,%1,%2,%3}, [%4];"
                 : "=r"(r[0]), "=r"(r[1]), "=r"(r[2]), "=r"(r[3]) : "r"(addr));
}
__device__ __forceinline__ void cpa16(uint32_t s, const void* g) {
    asm volatile("cp.async.cg.shared.global [%0], [%1], 16;" :: "r"(s), "l"(g));
}
__device__ __forceinline__ void cpa_commit() {
    asm volatile("cp.async.commit_group;" ::: "memory");
}
template <int N>
__device__ __forceinline__ void cpa_wait() {
    asm volatile("cp.async.wait_group %0;" :: "n"(N) : "memory");
}
// byte offset of (row l, elem ko[0..127]) in a staged tile (2B elems, 128B rows)
__device__ __forceinline__ uint32_t bofs(int l, int ko) {
    return ((uint32_t)(ko >> 6) << 13) +
           ((((uint32_t)l << 7) + (uint32_t)((ko & 63) << 1)) ^ (uint32_t)((l & 7) << 4));
}

// ---------------------------------------------------------------------------
// K0: W -> transposed bf16 hi/lo (for k1) + fp16 copy (for k5)
// ---------------------------------------------------------------------------
__global__ __launch_bounds__(256) void k0_wt(const float* __restrict__ W) {
    __shared__ float tile[32][33];
    int n0 = blockIdx.x * 32, h0 = blockIdx.y * 32;
    int tx = threadIdx.x & 31, ty = threadIdx.x >> 5;
    #pragma unroll
    for (int r = 0; r < 4; r++) {
        int h = h0 + ty + r * 8;
        float v = W[(size_t)h * K2 + n0 + tx];
        tile[ty + r * 8][tx] = v;
        g_W16[(size_t)h * K2 + n0 + tx] = __float2half_rn(v);
    }
    __syncthreads();
    #pragma unroll
    for (int r = 0; r < 4; r++) {
        int n = n0 + ty + r * 8;
        float x = tile[tx][ty + r * 8];
        __nv_bfloat16 h = __float2bfloat16_rn(x);
        g_Wt_h[(size_t)n * HD + h0 + tx] = h;
        g_Wt_l[(size_t)n * HD + h0 + tx] = __float2bfloat16_rn(x - __bfloat162float(h));
    }
}

// ---------------------------------------------------------------------------
__global__ __launch_bounds__(256) void k_bh(const float* __restrict__ hidden,
                                            const float* __restrict__ bias) {
    int w = (blockIdx.x * 256 + threadIdx.x) >> 5;
    int lane = threadIdx.x & 31;
    int b = w >> 6, l = w & 63;
    const float* hrow = hidden + (l * BB + b) * HD;
    float s = 0.f;
    for (int h = lane; h < HD; h += 32) s += bias[h] * hrow[h];
    #pragma unroll
    for (int o = 16; o; o >>= 1) s += __shfl_xor_sync(0xffffffffu, s, o);
    if (lane == 0) g_bh[w] = s;
}

// ---------------------------------------------------------------------------
// K1 (mma, bf16 3-term): Wh[m,n] = hidden_row(m) . Wt[n]; cp.async-staged B.
// grid (32,4), 256 thr. m-tile 128, n-tile 64, K=1024, chunk=64.
// ---------------------------------------------------------------------------
__global__ __launch_bounds__(256) void k1_mma(const float* __restrict__ hidden) {
    __shared__ __align__(128) uint8_t sm[32768];   // 2 bufs x (hi 8K + lo 8K)
    const int tid = threadIdx.x, w = tid >> 5, lane = tid & 31;
    const int grp = lane >> 2, tig = lane & 3;
    const int m0 = blockIdx.y * 128 + w * 16;
    const int n0 = blockIdx.x * 64;
    uint32_t sbase = smem_u32(sm);
    int mA = m0 + grp, mB = mA + 8;
    const float* row0 = hidden + (size_t)((mA & 63) * BB + (mA >> 6)) * HD;
    const float* row1 = hidden + (size_t)((mB & 63) * BB + (mB >> 6)) * HD;

    const int srow = tid >> 2, skp = (tid & 3) * 16;
    const __nv_bfloat16* sh = g_Wt_h + (size_t)(n0 + srow) * HD + skp;
    const __nv_bfloat16* sl = g_Wt_l + (size_t)(n0 + srow) * HD + skp;
    const uint32_t so1 = bofs(srow, skp), so2 = bofs(srow, skp + 8);

    // stage chunk 0 -> buf 0
    cpa16(sbase + so1, sh);           cpa16(sbase + so2, sh + 8);
    cpa16(sbase + so1 + 8192, sl);    cpa16(sbase + so2 + 8192, sl + 8);
    cpa_commit();

    float d[8][4];
    #pragma unroll
    for (int i = 0; i < 8; i++) { d[i][0]=d[i][1]=d[i][2]=d[i][3]=0.f; }

    float2 nv0 = *(const float2*)(row0 + tig * 2);
    float2 nv1 = *(const float2*)(row1 + tig * 2);
    float2 nv2 = *(const float2*)(row0 + tig * 2 + 8);
    float2 nv3 = *(const float2*)(row1 + tig * 2 + 8);

    for (int c = 0; c < 16; c++) {
        uint32_t bb = (uint32_t)(c & 1) * 16384;
        if (c < 15) {
            uint32_t db = sbase + (uint32_t)((c + 1) & 1) * 16384;
            const __nv_bfloat16* nh = sh + (c + 1) * 64;
            const __nv_bfloat16* nl = sl + (c + 1) * 64;
            cpa16(db + so1, nh);         cpa16(db + so2, nh + 8);
            cpa16(db + so1 + 8192, nl);  cpa16(db + so2 + 8192, nl + 8);
            cpa_commit();
            cpa_wait<1>();
        } else {
            cpa_wait<0>();
        }
        __syncthreads();
        #pragma unroll
        for (int ks = 0; ks < 4; ks++) {
            float2 v0 = nv0, v1 = nv1, v2 = nv2, v3 = nv3;
            int g = c * 4 + ks;
            if (g < 63) {
                const float* a0 = row0 + (g + 1) * 16 + tig * 2;
                const float* a1 = row1 + (g + 1) * 16 + tig * 2;
                nv0 = *(const float2*)a0;       nv1 = *(const float2*)a1;
                nv2 = *(const float2*)(a0 + 8); nv3 = *(const float2*)(a1 + 8);
            }
            uint32_t ah[4], al[4];
            split2(v0.x, v0.y, ah[0], al[0]);
            split2(v1.x, v1.y, ah[1], al[1]);
            split2(v2.x, v2.y, ah[2], al[2]);
            split2(v3.x, v3.y, ah[3], al[3]);
            int kol = ks * 16 + (lane & 8);
            uint32_t bh4[4][4], bl4[4][4];
            #pragma unroll
            for (int np = 0; np < 4; np++) {
                int lr = np * 16 + (lane & 7) + ((lane >> 1) & 8);
                uint32_t addr = sbase + bb + bofs(lr, kol);
                ldmx4(bh4[np], addr);
                ldmx4(bl4[np], addr + 8192);
            }
            #pragma unroll
            for (int np = 0; np < 4; np++) {
                mma_bf16(d[2*np],   ah, bh4[np][0], bh4[np][1]);
                mma_bf16(d[2*np+1], ah, bh4[np][2], bh4[np][3]);
            }
            #pragma unroll
            for (int np = 0; np < 4; np++) {
                mma_bf16(d[2*np],   al, bh4[np][0], bh4[np][1]);
                mma_bf16(d[2*np+1], al, bh4[np][2], bh4[np][3]);
            }
            #pragma unroll
            for (int np = 0; np < 4; np++) {
                mma_bf16(d[2*np],   ah, bl4[np][0], bl4[np][1]);
                mma_bf16(d[2*np+1], ah, bl4[np][2], bl4[np][3]);
            }
        }
        __syncthreads();
    }
    #pragma unroll
    for (int nt = 0; nt < 8; nt++) {
        int np = n0 + nt * 8 + tig * 2;
        uint32_t h01, l01, h23, l23;
        split2(d[nt][0], d[nt][1], h01, l01);
        split2(d[nt][2], d[nt][3], h23, l23);
        *(uint32_t*)(g_Wh_h + (size_t)mA * K2 + np) = h01;
        *(uint32_t*)(g_Wh_l + (size_t)mA * K2 + np) = l01;
        *(uint32_t*)(g_Wh_h + (size_t)mB * K2 + np) = h23;
        *(uint32_t*)(g_Wh_l + (size_t)mB * K2 + np) = l23;
    }
}

// ---------------------------------------------------------------------------
// K2 (mma, bf16 3-term): scores[l,s] = bh[l] + enc @ Wh^T. A prefetched 1 step.
// ---------------------------------------------------------------------------
__global__ __launch_bounds__(512) void k2_mma(const float* __restrict__ enc) {
    extern __shared__ __align__(128) uint8_t sm[];
    const int tid = threadIdx.x, w = tid >> 5, lane = tid & 31;
    const int grp = lane >> 2, tig = lane & 3;
    const int b = blockIdx.y;
    const int sW = blockIdx.x * 256 + w * 16;
    uint32_t sbase = smem_u32(sm);
    const float* encb = enc + (size_t)b * SS * K2;
    const __nv_bfloat16* Bh = g_Wh_h + (size_t)b * 64 * K2;
    const __nv_bfloat16* Bl = g_Wh_l + (size_t)b * 64 * K2;

    const int q0 = tid, q1 = tid + 512;
    const int l0q = q0 >> 4, ko0q = (q0 & 15) * 8;
    const int l1q = q1 >> 4, ko1q = (q1 & 15) * 8;

    {
        uint4 a  = *(const uint4*)(Bh + (size_t)l0q * K2 + ko0q);
        uint4 bq = *(const uint4*)(Bh + (size_t)l1q * K2 + ko1q);
        uint4 cq = *(const uint4*)(Bl + (size_t)l0q * K2 + ko0q);
        uint4 dq = *(const uint4*)(Bl + (size_t)l1q * K2 + ko1q);
        *(uint4*)(sm + bofs(l0q, ko0q)) = a;
        *(uint4*)(sm + bofs(l1q, ko1q)) = bq;
        *(uint4*)(sm + 16384 + bofs(l0q, ko0q)) = cq;
        *(uint4*)(sm + 16384 + bofs(l1q, ko1q)) = dq;
    }
    __syncthreads();

    float d[8][4];
    #pragma unroll
    for (int i = 0; i < 8; i++) { d[i][0]=d[i][1]=d[i][2]=d[i][3]=0.f; }

    const float* arow = encb + (size_t)(sW + grp) * K2 + tig * 2;
    float2 nv0 = *(const float2*)(arow);
    float2 nv1 = *(const float2*)(arow + 8 * K2);
    float2 nv2 = *(const float2*)(arow + 8);
    float2 nv3 = *(const float2*)(arow + 8 * K2 + 8);

    for (int c = 0; c < 16; c++) {
        int p = c & 1;
        uint4 ph0, ph1, pl0, pl1;
        if (c < 15) {
            int kb = (c + 1) * 128;
            ph0 = *(const uint4*)(Bh + (size_t)l0q * K2 + kb + ko0q);
            ph1 = *(const uint4*)(Bh + (size_t)l1q * K2 + kb + ko1q);
            pl0 = *(const uint4*)(Bl + (size_t)l0q * K2 + kb + ko0q);
            pl1 = *(const uint4*)(Bl + (size_t)l1q * K2 + kb + ko1q);
        }
        #pragma unroll
        for (int ks = 0; ks < 8; ks++) {
            float2 v0 = nv0, v1 = nv1, v2 = nv2, v3 = nv3;
            int g = c * 8 + ks;
            if (g < 127) {
                const float* ap = arow + (g + 1) * 16;
                nv0 = *(const float2*)(ap);
                nv1 = *(const float2*)(ap + 8 * K2);
                nv2 = *(const float2*)(ap + 8);
                nv3 = *(const float2*)(ap + 8 * K2 + 8);
            }
            uint32_t ah[4], al[4];
            split2(v0.x, v0.y, ah[0], al[0]);
            split2(v1.x, v1.y, ah[1], al[1]);
            split2(v2.x, v2.y, ah[2], al[2]);
            split2(v3.x, v3.y, ah[3], al[3]);
            int kol = ks * 16 + (lane & 8);
            uint32_t bh4[4][4], bl4[4][4];
            #pragma unroll
            for (int np = 0; np < 4; np++) {
                int lr = np * 16 + (lane & 7) + ((lane >> 1) & 8);
                uint32_t addr = sbase + (uint32_t)p * 32768 + bofs(lr, kol);
                ldmx4(bh4[np], addr);
                ldmx4(bl4[np], addr + 16384);
            }
            #pragma unroll
            for (int np = 0; np < 4; np++) {
                mma_bf16(d[2*np],   ah, bh4[np][0], bh4[np][1]);
                mma_bf16(d[2*np+1], ah, bh4[np][2], bh4[np][3]);
            }
            #pragma unroll
            for (int np = 0; np < 4; np++) {
                mma_bf16(d[2*np],   al, bh4[np][0], bh4[np][1]);
                mma_bf16(d[2*np+1], al, bh4[np][2], bh4[np][3]);
            }
            #pragma unroll
            for (int np = 0; np < 4; np++) {
                mma_bf16(d[2*np],   ah, bl4[np][0], bl4[np][1]);
                mma_bf16(d[2*np+1], ah, bl4[np][2], bl4[np][3]);
            }
        }
        if (c < 15) {
            __syncthreads();
            uint32_t bo = (uint32_t)(p ^ 1) * 32768;
            *(uint4*)(sm + bo + bofs(l0q, ko0q)) = ph0;
            *(uint4*)(sm + bo + bofs(l1q, ko1q)) = ph1;
            *(uint4*)(sm + bo + 16384 + bofs(l0q, ko0q)) = pl0;
            *(uint4*)(sm + bo + 16384 + bofs(l1q, ko1q)) = pl1;
            __syncthreads();
        }
    }
    #pragma unroll
    for (int nt = 0; nt < 8; nt++) {
        int li = nt * 8 + tig * 2;
        float b0v = g_bh[b * 64 + li], b1v = g_bh[b * 64 + li + 1];
        size_t r0 = (size_t)(b * 64 + li) * SS, r1 = r0 + SS;
        int sl = sW + grp;
        g_scores[r0 + sl]     = d[nt][0] + b0v;
        g_scores[r1 + sl]     = d[nt][1] + b1v;
        g_scores[r0 + sl + 8] = d[nt][2] + b0v;
        g_scores[r1 + sl + 8] = d[nt][3] + b1v;
    }
}

// ---------------------------------------------------------------------------
// K3a: per-row max & 1/sum
// ---------------------------------------------------------------------------
__global__ __launch_bounds__(256) void k3a() {
    int row = blockIdx.x, t = threadIdx.x;
    const float4* p = (const float4*)(g_scores + (size_t)row * SS) + t;
    float4 v[4];
    #pragma unroll
    for (int i = 0; i < 4; i++) v[i] = p[i * 256];
    float m = -1e30f;
    #pragma unroll
    for (int i = 0; i < 4; i++) {
        m = fmaxf(m, fmaxf(fmaxf(v[i].x, v[i].y), fmaxf(v[i].z, v[i].w)));
    }
    __shared__ float red[256];
    red[t] = m; __syncthreads();
    #pragma unroll
    for (int o = 128; o; o >>= 1) { if (t < o) red[t] = fmaxf(red[t], red[t + o]); __syncthreads(); }
    m = red[0]; __syncthreads();
    float s = 0.f;
    #pragma unroll
    for (int i = 0; i < 4; i++) {
        s += expf(v[i].x - m) + expf(v[i].y - m) + expf(v[i].z - m) + expf(v[i].w - m);
    }
    red[t] = s; __syncthreads();
    #pragma unroll
    for (int o = 128; o; o >>= 1) { if (t < o) red[t] += red[t + o]; __syncthreads(); }
    if (t == 0) { g_m[row] = m; g_inv[row] = 1.f / red[0]; }
}

// ---------------------------------------------------------------------------
// K3b: weights -> out_w [B,S,L] (coalesced) + fp16 hi/lo scratch [row][s]
// grid (SS/128, BB), 256 thr: 4 threads per l-row, 32 s each.
// ---------------------------------------------------------------------------
__global__ __launch_bounds__(256) void k3b(float* __restrict__ out_w) {
    int b = blockIdx.y, s0 = blockIdx.x * 128;
    int t = threadIdx.x, l = t >> 2, q = t & 3;
    int row = b * 64 + l;
    float m = g_m[row], inv = g_inv[row];
    int sb0 = s0 + q * 32;
    const float* p = g_scores + (size_t)row * SS + sb0;
    uint32_t hb[16], lb[16];
    #pragma unroll
    for (int j = 0; j < 16; j++) {
        float2 x = *(const float2*)(p + j * 2);
        float w0 = expf(x.x - m) * inv;
        float w1 = expf(x.y - m) * inv;
        out_w[((size_t)b * SS + sb0 + j * 2) * LL + l]     = w0;
        out_w[((size_t)b * SS + sb0 + j * 2 + 1) * LL + l] = w1;
        split2h(w0, w1, hb[j], lb[j]);
    }
    size_t wo = (size_t)row * SS + sb0;
    #pragma unroll
    for (int j = 0; j < 4; j++) {
        *(uint4*)(g_w_h + wo + j * 8) = make_uint4(hb[4*j], hb[4*j+1], hb[4*j+2], hb[4*j+3]);
        *(uint4*)(g_w_l + wo + j * 8) = make_uint4(lb[4*j], lb[4*j+1], lb[4*j+2], lb[4*j+3]);
    }
}

// ---------------------------------------------------------------------------
// K4 (mma, fp16 2-term): ctx2[l,k] = sum_s w[l,s] enc[s,k]. A prefetched 1 step.
// ---------------------------------------------------------------------------
__global__ __launch_bounds__(512) void k4_mma(const float* __restrict__ enc) {
    extern __shared__ __align__(128) uint8_t sm[];
    const int tid = threadIdx.x, w = tid >> 5, lane = tid & 31;
    const int grp = lane >> 2, tig = lane & 3;
    const int wk = w & 7, sgrp = w >> 3;
    const int b = blockIdx.y;
    const int kb0 = blockIdx.x * 128;
    const int kW = kb0 + wk * 16;
    uint32_t sbase = smem_u32(sm);
    const float* encb = enc + (size_t)b * SS * K2;
    const __half* Bh = g_w_h + (size_t)b * 64 * SS;
    const __half* Bl = g_w_l + (size_t)b * 64 * SS;

    const int q0 = tid, q1 = tid + 512;
    const int l0q = q0 >> 4, ko0q = (q0 & 15) * 8;
    const int l1q = q1 >> 4, ko1q = (q1 & 15) * 8;

    {
        uint4 a  = *(const uint4*)(Bh + (size_t)l0q * SS + ko0q);
        uint4 bq = *(const uint4*)(Bh + (size_t)l1q * SS + ko1q);
        uint4 cq = *(const uint4*)(Bl + (size_t)l0q * SS + ko0q);
        uint4 dq = *(const uint4*)(Bl + (size_t)l1q * SS + ko1q);
        *(uint4*)(sm + bofs(l0q, ko0q)) = a;
        *(uint4*)(sm + bofs(l1q, ko1q)) = bq;
        *(uint4*)(sm + 16384 + bofs(l0q, ko0q)) = cq;
        *(uint4*)(sm + 16384 + bofs(l1q, ko1q)) = dq;
    }
    __syncthreads();

    float d[8][4];
    #pragma unroll
    for (int i = 0; i < 8; i++) { d[i][0]=d[i][1]=d[i][2]=d[i][3]=0.f; }

    // A prefetch state (8 floats)
    float na[8];
    {
        int s0 = sgrp * 16;
        const float* ap = encb + (size_t)(s0 + tig * 2) * K2 + kW + grp;
        na[0] = ap[0];           na[1] = ap[K2];
        na[2] = ap[8];           na[3] = ap[K2 + 8];
        na[4] = ap[8 * K2];      na[5] = ap[9 * K2];
        na[6] = ap[8 * K2 + 8];  na[7] = ap[9 * K2 + 8];
    }

    for (int c = 0; c < 32; c++) {
        int p = c & 1;
        uint4 ph0, ph1, pl0, pl1;
        if (c < 31) {
            int s1 = (c + 1) * 128;
            ph0 = *(const uint4*)(Bh + (size_t)l0q * SS + s1 + ko0q);
            ph1 = *(const uint4*)(Bh + (size_t)l1q * SS + s1 + ko1q);
            pl0 = *(const uint4*)(Bl + (size_t)l0q * SS + s1 + ko0q);
            pl1 = *(const uint4*)(Bl + (size_t)l1q * SS + s1 + ko1q);
        }
        #pragma unroll
        for (int ks2 = 0; ks2 < 4; ks2++) {
            float a8[8];
            #pragma unroll
            for (int i = 0; i < 8; i++) a8[i] = na[i];
            int g = c * 4 + ks2;
            if (g < 127) {
                int gn = g + 1;
                int s0 = (gn >> 2) * 128 + (((gn & 3) * 2 + sgrp)) * 16;
                const float* ap = encb + (size_t)(s0 + tig * 2) * K2 + kW + grp;
                na[0] = ap[0];           na[1] = ap[K2];
                na[2] = ap[8];           na[3] = ap[K2 + 8];
                na[4] = ap[8 * K2];      na[5] = ap[9 * K2];
                na[6] = ap[8 * K2 + 8];  na[7] = ap[9 * K2 + 8];
            }
            uint32_t ah[4];
            ah[0] = packh(a8[0], a8[1]);
            ah[1] = packh(a8[2], a8[3]);
            ah[2] = packh(a8[4], a8[5]);
            ah[3] = packh(a8[6], a8[7]);
            int ks = ks2 * 2 + sgrp;
            int kol = ks * 16 + (lane & 8);
            uint32_t bh4[4][4], bl4[4][4];
            #pragma unroll
            for (int np = 0; np < 4; np++) {
                int lr = np * 16 + (lane & 7) + ((lane >> 1) & 8);
                uint32_t addr = sbase + (uint32_t)p * 32768 + bofs(lr, kol);
                ldmx4(bh4[np], addr);
                ldmx4(bl4[np], addr + 16384);
            }
            #pragma unroll
            for (int np = 0; np < 4; np++) {
                mma_fp16(d[2*np],   ah, bh4[np][0], bh4[np][1]);
                mma_fp16(d[2*np+1], ah, bh4[np][2], bh4[np][3]);
            }
            #pragma unroll
            for (int np = 0; np < 4; np++) {
                mma_fp16(d[2*np],   ah, bl4[np][0], bl4[np][1]);
                mma_fp16(d[2*np+1], ah, bl4[np][2], bl4[np][3]);
            }
        }
        if (c < 31) {
            __syncthreads();
            uint32_t bo = (uint32_t)(p ^ 1) * 32768;
            *(uint4*)(sm + bo + bofs(l0q, ko0q)) = ph0;
            *(uint4*)(sm + bo + bofs(l1q, ko1q)) = ph1;
            *(uint4*)(sm + bo + 16384 + bofs(l0q, ko0q)) = pl0;
            *(uint4*)(sm + bo + 16384 + bofs(l1q, ko1q)) = pl1;
            __syncthreads();
        }
    }

    __syncthreads();
    float* acc = (float*)sm;
    {
        int base = sgrp * 8192;
        #pragma unroll
        for (int nt = 0; nt < 8; nt++) {
            int li = nt * 8 + tig * 2;
            int kr = wk * 16 + grp;
            acc[base + li * 128 + kr]           = d[nt][0];
            acc[base + (li + 1) * 128 + kr]     = d[nt][1];
            acc[base + li * 128 + kr + 8]       = d[nt][2];
            acc[base + (li + 1) * 128 + kr + 8] = d[nt][3];
        }
    }
    __syncthreads();
    {
        int l = tid >> 3, kq = (tid & 7) * 16;
        const float* s0p = acc + l * 128 + kq;
        const float* s1p = acc + 8192 + l * 128 + kq;
        uint32_t hb[8], lb[8];
        #pragma unroll
        for (int j = 0; j < 8; j++) {
            float x0 = s0p[2 * j] + s1p[2 * j];
            float x1 = s0p[2 * j + 1] + s1p[2 * j + 1];
            split2h(x0, x1, hb[j], lb[j]);
        }
        size_t ro = (size_t)(b * 64 + l) * K2 + kb0 + kq;
        *(uint4*)(g_c2_h + ro)     = make_uint4(hb[0], hb[1], hb[2], hb[3]);
        *(uint4*)(g_c2_h + ro + 8) = make_uint4(hb[4], hb[5], hb[6], hb[7]);
        *(uint4*)(g_c2_l + ro)     = make_uint4(lb[0], lb[1], lb[2], lb[3]);
        *(uint4*)(g_c2_l + ro + 8) = make_uint4(lb[4], lb[5], lb[6], lb[7]);
    }
}

// ---------------------------------------------------------------------------
// K5 (mma, fp16 2-term): out[m,h] = bias[h] + sum_k ctx2[m,k] W[h,k]
// B from pre-converted g_W16.
// ---------------------------------------------------------------------------
__global__ __launch_bounds__(256) void k5_mma(const float* __restrict__ bias,
                                              float* __restrict__ out) {
    const int tid = threadIdx.x, w = tid >> 5, lane = tid & 31;
    const int grp = lane >> 2, tig = lane & 3;
    const int m0 = blockIdx.y * 128 + w * 16;
    const int n0 = blockIdx.x * 32;
    int mA = m0 + grp, mB = mA + 8;
    const uint32_t* a0h = (const uint32_t*)(g_c2_h + (size_t)mA * K2) + tig;
    const uint32_t* a0l = (const uint32_t*)(g_c2_l + (size_t)mA * K2) + tig;
    const uint32_t* a1h = (const uint32_t*)(g_c2_h + (size_t)mB * K2) + tig;
    const uint32_t* a1l = (const uint32_t*)(g_c2_l + (size_t)mB * K2) + tig;

    float d[4][4];
    #pragma unroll
    for (int i = 0; i < 4; i++) { d[i][0]=d[i][1]=d[i][2]=d[i][3]=0.f; }

    #pragma unroll 2
    for (int k0 = 0; k0 < K2; k0 += 16) {
        int ku = k0 >> 1;
        uint32_t ah[4], al[4];
        ah[0] = a0h[ku];     al[0] = a0l[ku];
        ah[1] = a1h[ku];     al[1] = a1l[ku];
        ah[2] = a0h[ku + 4]; al[2] = a0l[ku + 4];
        ah[3] = a1h[ku + 4]; al[3] = a1l[ku + 4];
        uint32_t bh0[4], bh1[4];
        #pragma unroll
        for (int nt = 0; nt < 4; nt++) {
            const __half* wp = g_W16 + (size_t)(n0 + nt * 8 + grp) * K2 + k0 + 2 * tig;
            bh0[nt] = *(const uint32_t*)(wp);
            bh1[nt] = *(const uint32_t*)(wp + 8);
        }
        #pragma unroll
        for (int nt = 0; nt < 4; nt++) mma_fp16(d[nt], ah, bh0[nt], bh1[nt]);
        #pragma unroll
        for (int nt = 0; nt < 4; nt++) mma_fp16(d[nt], al, bh0[nt], bh1[nt]);
    }
    #pragma unroll
    for (int nt = 0; nt < 4; nt++) {
        int hp = n0 + nt * 8 + tig * 2;
        float2 bv = *(const float2*)(bias + hp);
        float2 o0 = {d[nt][0] + bv.x, d[nt][1] + bv.y};
        float2 o1 = {d[nt][2] + bv.x, d[nt][3] + bv.y};
        *(float2*)(out + (size_t)mA * HD + hp) = o0;
        *(float2*)(out + (size_t)mB * HD + hp) = o1;
    }
}

// ---------------------------------------------------------------------------
extern "C" void kernel_launch(void* const* d_in, const int* in_sizes, int n_in,
                              void* d_out, int out_size) {
    (void)in_sizes; (void)n_in; (void)out_size;
    const float* hidden = (const float*)d_in[0];
    const float* enc    = (const float*)d_in[1];
    const float* W      = (const float*)d_in[2];
    const float* bias   = (const float*)d_in[3];
    float* out_ctx = (float*)d_out;
    float* out_w   = (float*)d_out + (size_t)BB * LL * HD;

    cudaFuncSetAttribute(k2_mma, cudaFuncAttributeMaxDynamicSharedMemorySize, 65536);
    cudaFuncSetAttribute(k4_mma, cudaFuncAttributeMaxDynamicSharedMemorySize, 65536);

    k0_wt<<<dim3(64, 32), 256>>>(W);
    k_bh<<<64, 256>>>(hidden, bias);
    k1_mma<<<dim3(32, 4), 256>>>(hidden);
    k2_mma<<<dim3(16, 8), 512, 65536>>>(enc);
    k3a<<<512, 256>>>();
    k3b<<<dim3(32, 8), 256>>>(out_w);
    k4_mma<<<dim3(16, 8), 512, 65536>>>(enc);
    k5_mma<<<dim3(32, 4), 256>>>(bias, out_ctx);
}